// round 14
// baseline (speedup 1.0000x reference)
#include <cuda_runtime.h>
#include <cuda_fp16.h>
#include <math.h>

#define NSEG  125000
#define VROWS 1000000

typedef unsigned long long u64;

// ---------------- packed f32x2 helpers (sm_100+) ----------------------------
__device__ __forceinline__ u64 pack2(float x) {
    u64 r; unsigned xi = __float_as_uint(x);
    asm("mov.b64 %0, {%1, %1};" : "=l"(r) : "r"(xi));
    return r;
}
__device__ __forceinline__ void unpack2(u64 v, float& a, float& b) {
    unsigned lo, hi;
    asm("mov.b64 {%0, %1}, %2;" : "=r"(lo), "=r"(hi) : "l"(v));
    a = __uint_as_float(lo); b = __uint_as_float(hi);
}
__device__ __forceinline__ void ffma2(u64& acc, u64 a, u64 b) {
    asm("fma.rn.f32x2 %0, %1, %2, %0;" : "+l"(acc) : "l"(a), "l"(b));
}

// ---------------- scratch (device globals; no allocation allowed) ----------
static __device__ __half g_z2[(size_t)VROWS * 64];  // z2 pre-BN activations (fp16)
static __device__ float g_q [(size_t)NSEG * 64];    // per-segment query
static __device__ float g_Pt[(size_t)NSEG * 64];    // Wk_top @ q   (h2 part)
static __device__ float g_Pb[(size_t)NSEG * 128];   // Wk_bot @ q   (x_mod part)
static __device__ float g_c [NSEG];                 // bk . q
static __device__ float g_X [VROWS];                // per-row scores
static __device__ float g_gram[1024];               // X^T X  (32x32)
static __device__ float g_sx[32];                   // sum of x_proj rows
static __device__ float g_stats2[128];              // sum(64) | sumsq(64)
static __device__ float g_s1[64], g_t1[64], g_s2[64], g_t2[64];

// ---------------- init: zero accumulators ----------------------------------
__global__ void k_init() {
    int t = threadIdx.x;
    for (int i = t; i < 1024; i += 256) g_gram[i] = 0.f;
    if (t < 32)  g_sx[t] = 0.f;
    if (t < 128) g_stats2[t] = 0.f;
}

// ---------------- Gram pass (syrk in shared, NO shuffles) ------------------
// 1024 rows/block in 8 stages of 128. Thread t owns Gram entries 4t..4t+3.
__global__ void __launch_bounds__(256) k_gram2(const float* __restrict__ xp) {
    __shared__ __align__(16) float sX[128 * 36];   // pad 36: LDS.128-aligned rows
    int t = threadIdx.x;
    int base = blockIdx.x * 1024;
    int i0 = (4 * t) >> 5;        // Gram row
    int j0 = (4 * t) & 31;        // Gram col (multiple of 4)
    float acc0 = 0.f, acc1 = 0.f, acc2 = 0.f, acc3 = 0.f;
    float sxl = 0.f;

    for (int stage = 0; stage < 8; stage++) {
        int rbase = base + stage * 128;
        int nr = VROWS - rbase;
        if (nr <= 0) break;
        if (nr > 128) nr = 128;
        __syncthreads();                        // previous-stage reads done
        const float4* xg = (const float4*)(xp + (size_t)rbase * 32);
        for (int idx = t; idx < nr * 8; idx += 256) {
            float4 v = xg[idx];
            int r = idx >> 3, c = (idx & 7) << 2;
            float* d = &sX[r * 36 + c];
            d[0] = v.x; d[1] = v.y; d[2] = v.z; d[3] = v.w;
        }
        __syncthreads();
#pragma unroll 4
        for (int r = 0; r < nr; r++) {
            float  xi = sX[r * 36 + i0];                    // broadcast
            float4 xj = *(const float4*)&sX[r * 36 + j0];   // LDS.128
            acc0 = fmaf(xi, xj.x, acc0);
            acc1 = fmaf(xi, xj.y, acc1);
            acc2 = fmaf(xi, xj.z, acc2);
            acc3 = fmaf(xi, xj.w, acc3);
        }
        if (t < 32) {                                       // column sums
            for (int r = 0; r < nr; r++) sxl += sX[r * 36 + t];
        }
    }
    atomicAdd(&g_gram[4 * t + 0], acc0);
    atomicAdd(&g_gram[4 * t + 1], acc1);
    atomicAdd(&g_gram[4 * t + 2], acc2);
    atomicAdd(&g_gram[4 * t + 3], acc3);
    if (t < 32) atomicAdd(&g_sx[t], sxl);
}

// ---------------- finalize BN1 from Gram -----------------------------------
__global__ void k_fing(const float* __restrict__ W1, const float* __restrict__ b1,
                       const float* __restrict__ g1, const float* __restrict__ beta1) {
    __shared__ float sG[1024];
    __shared__ float sx[32];
    int t = threadIdx.x;                 // 64 threads, one per channel
    for (int i = t; i < 1024; i += 64) sG[i] = g_gram[i];
    if (t < 32) sx[t] = g_sx[t];
    __syncthreads();
    float w[32];
#pragma unroll
    for (int i = 0; i < 32; i++) w[i] = W1[i * 64 + t];
    float wgw = 0.f, wsx = 0.f;
    for (int i = 0; i < 32; i++) {
        float ti = 0.f;
#pragma unroll
        for (int k = 0; k < 32; k++) ti = fmaf(sG[i * 32 + k], w[k], ti);
        wgw = fmaf(w[i], ti, wgw);
        wsx = fmaf(w[i], sx[i], wsx);
    }
    float bj = b1[t];
    const float invV = 1.f / (float)VROWS;
    float mu  = wsx * invV + bj;
    float ez2 = (wgw + 2.f * bj * wsx) * invV + bj * bj;
    float var = ez2 - mu * mu;
    float s   = g1[t] * rsqrtf(var + 1e-5f);
    g_s1[t] = s;
    g_t1[t] = beta1[t] - mu * s;
}

// ---------------- mlp2: tiled GEMM1 -> BN1/ReLU -> tiled GEMM2 -------------
// 256 rows/block, 256 threads, 8 rows x 8 cols per thread. z2 stored fp16.
__global__ void __launch_bounds__(256, 2) k_mlp2(const float* __restrict__ xp,
                                                 const float* __restrict__ W1,
                                                 const float* __restrict__ b1,
                                                 const float* __restrict__ W2,
                                                 const float* __restrict__ b2) {
    extern __shared__ float sm[];
    float* sB   = sm;                    // 64 x 264 (x^T rows 0..31, then h1^T rows 0..63)
    float* sW1  = sm + 64 * 264;         // 2048
    float* sW2  = sW1 + 2048;            // 4096
    float* sS1  = sW2 + 4096;            // 64
    float* sT1  = sS1 + 64;              // 64
    float* sSum = sT1 + 64;              // 64
    float* sSq  = sSum + 64;             // 64

    int t = threadIdx.x;
    int base = blockIdx.x * 256;
    int nrows = VROWS - base; if (nrows > 256) nrows = 256;
    int cg = t & 7, rg = t >> 3;

    for (int i = t; i < 512;  i += 256) ((float4*)sW1)[i] = ((const float4*)W1)[i];
    for (int i = t; i < 1024; i += 256) ((float4*)sW2)[i] = ((const float4*)W2)[i];
    if (t < 64) { sS1[t] = g_s1[t]; sT1[t] = g_t1[t]; sSum[t] = 0.f; sSq[t] = 0.f; }

    // stage x transposed: sB[c][r] = x[base+r][c] (zero-fill past nrows)
    {
        const float4* xg = (const float4*)(xp + (size_t)base * 32);
        for (int i = t; i < 2048; i += 256) {
            int r = i >> 3, c4 = (i & 7) << 2;
            float4 v = (r < nrows) ? xg[i] : make_float4(0.f, 0.f, 0.f, 0.f);
            sB[(c4 + 0) * 264 + r] = v.x;
            sB[(c4 + 1) * 264 + r] = v.y;
            sB[(c4 + 2) * 264 + r] = v.z;
            sB[(c4 + 3) * 264 + r] = v.w;
        }
    }
    __syncthreads();

    u64 acc[32];
    {
        const u64* bp = (const u64*)b1;
        u64 c0 = bp[cg * 4 + 0], c1 = bp[cg * 4 + 1], c2 = bp[cg * 4 + 2], c3 = bp[cg * 4 + 3];
#pragma unroll
        for (int r = 0; r < 8; r++) { acc[r*4+0]=c0; acc[r*4+1]=c1; acc[r*4+2]=c2; acc[r*4+3]=c3; }
    }
#pragma unroll 4
    for (int k = 0; k < 32; k++) {
        float4 xa = *(const float4*)&sB[k * 264 + rg * 8];
        float4 xb = *(const float4*)&sB[k * 264 + rg * 8 + 4];
        ulonglong2 wA = *(const ulonglong2*)&sW1[k * 64 + cg * 8];
        ulonglong2 wB = *(const ulonglong2*)&sW1[k * 64 + cg * 8 + 4];
        float xs[8] = {xa.x, xa.y, xa.z, xa.w, xb.x, xb.y, xb.z, xb.w};
#pragma unroll
        for (int r = 0; r < 8; r++) {
            u64 xx = pack2(xs[r]);
            ffma2(acc[r*4+0], xx, wA.x);
            ffma2(acc[r*4+1], xx, wA.y);
            ffma2(acc[r*4+2], xx, wB.x);
            ffma2(acc[r*4+3], xx, wB.y);
        }
    }
    __syncthreads();                      // all reads of x^T done

    // BN1 + ReLU -> h1^T into sB (rows = channels 0..63)
#pragma unroll
    for (int cp = 0; cp < 4; cp++) {
        int c0 = cg * 8 + cp * 2;
        float s0 = sS1[c0], t0 = sT1[c0], s1 = sS1[c0 + 1], t1 = sT1[c0 + 1];
        float h0[8], h1[8];
#pragma unroll
        for (int r = 0; r < 8; r++) {
            float a, b; unpack2(acc[r*4+cp], a, b);
            h0[r] = fmaxf(fmaf(a, s0, t0), 0.f);
            h1[r] = fmaxf(fmaf(b, s1, t1), 0.f);
        }
        *(float4*)&sB[c0 * 264 + rg * 8]           = make_float4(h0[0], h0[1], h0[2], h0[3]);
        *(float4*)&sB[c0 * 264 + rg * 8 + 4]       = make_float4(h0[4], h0[5], h0[6], h0[7]);
        *(float4*)&sB[(c0 + 1) * 264 + rg * 8]     = make_float4(h1[0], h1[1], h1[2], h1[3]);
        *(float4*)&sB[(c0 + 1) * 264 + rg * 8 + 4] = make_float4(h1[4], h1[5], h1[6], h1[7]);
    }
    __syncthreads();

    {
        const u64* bp = (const u64*)b2;
        u64 c0 = bp[cg * 4 + 0], c1 = bp[cg * 4 + 1], c2 = bp[cg * 4 + 2], c3 = bp[cg * 4 + 3];
#pragma unroll
        for (int r = 0; r < 8; r++) { acc[r*4+0]=c0; acc[r*4+1]=c1; acc[r*4+2]=c2; acc[r*4+3]=c3; }
    }
#pragma unroll 4
    for (int k = 0; k < 64; k++) {
        float4 xa = *(const float4*)&sB[k * 264 + rg * 8];
        float4 xb = *(const float4*)&sB[k * 264 + rg * 8 + 4];
        ulonglong2 wA = *(const ulonglong2*)&sW2[k * 64 + cg * 8];
        ulonglong2 wB = *(const ulonglong2*)&sW2[k * 64 + cg * 8 + 4];
        float xs[8] = {xa.x, xa.y, xa.z, xa.w, xb.x, xb.y, xb.z, xb.w};
#pragma unroll
        for (int r = 0; r < 8; r++) {
            u64 xx = pack2(xs[r]);
            ffma2(acc[r*4+0], xx, wA.x);
            ffma2(acc[r*4+1], xx, wA.y);
            ffma2(acc[r*4+2], xx, wB.x);
            ffma2(acc[r*4+3], xx, wB.y);
        }
    }

    // store z2 (fp16) + accumulate BN2 stats (f32)
    float ss[8], qq[8];
#pragma unroll
    for (int i = 0; i < 8; i++) { ss[i] = 0.f; qq[i] = 0.f; }
#pragma unroll
    for (int r = 0; r < 8; r++) {
        int row = rg * 8 + r;
        if (row < nrows) {
            float a0, b0, a1, b1v, a2, b2v, a3, b3;
            unpack2(acc[r*4+0], a0, b0);
            unpack2(acc[r*4+1], a1, b1v);
            unpack2(acc[r*4+2], a2, b2v);
            unpack2(acc[r*4+3], a3, b3);
            __half2 h0 = __floats2half2_rn(a0, b0);
            __half2 h1 = __floats2half2_rn(a1, b1v);
            __half2 h2 = __floats2half2_rn(a2, b2v);
            __half2 h3 = __floats2half2_rn(a3, b3);
            uint4 pk = make_uint4(*(unsigned*)&h0, *(unsigned*)&h1,
                                  *(unsigned*)&h2, *(unsigned*)&h3);
            *(uint4*)(g_z2 + (size_t)(base + row) * 64 + cg * 8) = pk;
            ss[0] += a0; qq[0] += a0 * a0;  ss[1] += b0; qq[1] += b0 * b0;
            ss[2] += a1; qq[2] += a1 * a1;  ss[3] += b1v; qq[3] += b1v * b1v;
            ss[4] += a2; qq[4] += a2 * a2;  ss[5] += b2v; qq[5] += b2v * b2v;
            ss[6] += a3; qq[6] += a3 * a3;  ss[7] += b3; qq[7] += b3 * b3;
        }
    }
    const unsigned FULL = 0xffffffffu;
#pragma unroll
    for (int o = 8; o <= 16; o <<= 1) {
#pragma unroll
        for (int i = 0; i < 8; i++) {
            ss[i] += __shfl_xor_sync(FULL, ss[i], o);
            qq[i] += __shfl_xor_sync(FULL, qq[i], o);
        }
    }
    if ((t & 31) < 8) {                  // these lanes have lane == cg
#pragma unroll
        for (int c = 0; c < 8; c++) {
            atomicAdd(&sSum[cg * 8 + c], ss[c]);
            atomicAdd(&sSq [cg * 8 + c], qq[c]);
        }
    }
    __syncthreads();
    if (t < 64) {
        atomicAdd(&g_stats2[t],      sSum[t]);
        atomicAdd(&g_stats2[64 + t], sSq[t]);
    }
}

// ---------------- finalize BN2 ---------------------------------------------
__global__ void k_fin2(const float* __restrict__ g, const float* __restrict__ beta) {
    int c = threadIdx.x;
    if (c >= 64) return;
    float mu  = g_stats2[c] * (1.f / (float)VROWS);
    float var = g_stats2[64 + c] * (1.f / (float)VROWS) - mu * mu;
    float s   = g[c] * rsqrtf(var + 1e-5f);
    g_s2[c] = s;
    g_t2[c] = beta[c] - mu * s;
}

// ---------------- per-segment query q = x_main@Wq + bq ---------------------
__global__ void __launch_bounds__(64) k_q(const float* __restrict__ xm,
                                          const float* __restrict__ Wq,
                                          const float* __restrict__ bq) {
    __shared__ __align__(16) float sX[64 * 65];
    __shared__ __align__(16) float sW[4096];
    int t = threadIdx.x;
    int base = blockIdx.x * 64;
    int nrows = min(64, NSEG - base);

    for (int i = t; i < 1024; i += 64)
        ((float4*)sW)[i] = ((const float4*)Wq)[i];
    const float4* xg = (const float4*)(xm + (size_t)base * 64);
    for (int i = t; i < nrows * 16; i += 64) {
        float4 v = xg[i];
        int r = i >> 4, c = (i & 15) << 2;
        float* d = &sX[r * 65 + c];
        d[0] = v.x; d[1] = v.y; d[2] = v.z; d[3] = v.w;
    }
    __syncthreads();

    if (t >= nrows) return;
    int n = base + t;
    u64 acc[32];
    const u64* bp = (const u64*)bq;
#pragma unroll
    for (int j = 0; j < 32; j++) acc[j] = bp[j];
#pragma unroll 8
    for (int k = 0; k < 64; k++) {
        u64 xx = pack2(sX[t * 65 + k]);
        const ulonglong2* wr = (const ulonglong2*)(sW + k * 64);
#pragma unroll
        for (int jo = 0; jo < 16; jo++) {
            ulonglong2 w = wr[jo];
            ffma2(acc[2 * jo],     xx, w.x);
            ffma2(acc[2 * jo + 1], xx, w.y);
        }
    }
    ulonglong2* qo = (ulonglong2*)(g_q + (size_t)n * 64);
#pragma unroll
    for (int jo = 0; jo < 16; jo++)
        qo[jo] = make_ulonglong2(acc[2 * jo], acc[2 * jo + 1]);
}

// ---------------- P = Wk @ q (192), c = bk.q ; 4 segments/thread -----------
__global__ void __launch_bounds__(128) k_p(const float* __restrict__ Wk,
                                           const float* __restrict__ bk) {
    __shared__ float sW[12288];          // 48 KB: Wk row-major [192,64]
    int t = threadIdx.x;
    for (int i = t; i < 3072; i += 128) ((float4*)sW)[i] = ((const float4*)Wk)[i];
    __syncthreads();

    int n0 = blockIdx.x * 512 + t;
    int n1 = n0 + 128, n2 = n0 + 256, n3 = n0 + 384;
    bool v0 = n0 < NSEG, v1 = n1 < NSEG, v2 = n2 < NSEG, v3 = n3 < NSEG;
    const ulonglong2* q0 = (const ulonglong2*)(g_q + (size_t)(v0 ? n0 : 0) * 64);
    const ulonglong2* q1 = (const ulonglong2*)(g_q + (size_t)(v1 ? n1 : 0) * 64);
    const ulonglong2* q2 = (const ulonglong2*)(g_q + (size_t)(v2 ? n2 : 0) * 64);
    const ulonglong2* q3 = (const ulonglong2*)(g_q + (size_t)(v3 ? n3 : 0) * 64);

    // c = bk . q
    {
        const float4* bkr = (const float4*)bk;
        float c0 = 0.f, c1 = 0.f, c2 = 0.f, c3 = 0.f;
#pragma unroll
        for (int jo = 0; jo < 16; jo++) {
            float4 b4 = bkr[jo];
            float4 qa = ((const float4*)q0)[jo];
            float4 qb = ((const float4*)q1)[jo];
            float4 qc = ((const float4*)q2)[jo];
            float4 qd = ((const float4*)q3)[jo];
            c0 += qa.x * b4.x + qa.y * b4.y + qa.z * b4.z + qa.w * b4.w;
            c1 += qb.x * b4.x + qb.y * b4.y + qb.z * b4.z + qb.w * b4.w;
            c2 += qc.x * b4.x + qc.y * b4.y + qc.z * b4.z + qc.w * b4.w;
            c3 += qd.x * b4.x + qd.y * b4.y + qd.z * b4.z + qd.w * b4.w;
        }
        if (v0) g_c[n0] = c0;
        if (v1) g_c[n1] = c1;
        if (v2) g_c[n2] = c2;
        if (v3) g_c[n3] = c3;
    }

    for (int chunk = 0; chunk < 24; chunk++) {
        u64 a0[8], a1[8], a2[8], a3[8];
#pragma unroll
        for (int i = 0; i < 8; i++) { a0[i] = 0ull; a1[i] = 0ull; a2[i] = 0ull; a3[i] = 0ull; }
        for (int jo = 0; jo < 16; jo++) {
            ulonglong2 qa = q0[jo];     // L1 hit after first chunk
            ulonglong2 qb = q1[jo];
            ulonglong2 qc = q2[jo];
            ulonglong2 qd = q3[jo];
#pragma unroll
            for (int i = 0; i < 8; i++) {
                ulonglong2 w = ((const ulonglong2*)sW)[(chunk * 8 + i) * 16 + jo];
                ffma2(a0[i], qa.x, w.x); ffma2(a0[i], qa.y, w.y);
                ffma2(a1[i], qb.x, w.x); ffma2(a1[i], qb.y, w.y);
                ffma2(a2[i], qc.x, w.x); ffma2(a2[i], qc.y, w.y);
                ffma2(a3[i], qd.x, w.x); ffma2(a3[i], qd.y, w.y);
            }
        }
        int o = chunk * 8;
        float *d0, *d1, *d2, *d3;
        if (o < 64) { d0 = g_Pt + (size_t)n0 * 64 + o;  d1 = g_Pt + (size_t)n1 * 64 + o;
                      d2 = g_Pt + (size_t)n2 * 64 + o;  d3 = g_Pt + (size_t)n3 * 64 + o; }
        else        { d0 = g_Pb + (size_t)n0 * 128 + (o - 64); d1 = g_Pb + (size_t)n1 * 128 + (o - 64);
                      d2 = g_Pb + (size_t)n2 * 128 + (o - 64); d3 = g_Pb + (size_t)n3 * 128 + (o - 64); }
#pragma unroll
        for (int i = 0; i < 8; i++) {
            float lo, hi;
            if (v0) { unpack2(a0[i], lo, hi); d0[i] = lo + hi; }
            if (v1) { unpack2(a1[i], lo, hi); d1[i] = lo + hi; }
            if (v2) { unpack2(a2[i], lo, hi); d2[i] = lo + hi; }
            if (v3) { unpack2(a3[i], lo, hi); d3[i] = lo + hi; }
        }
    }
}

// ---------------- warp-per-segment, two-pass; float4 x_mod path ------------
// Lane l owns x_mod channels 4l..4l+3 (one float4). Same bytes, same chains
// as the R12 kernel — strictly fewer instructions.
__global__ void __launch_bounds__(256) k_seg(const float* __restrict__ x_mod,
                                             const int* __restrict__ csr,
                                             float* __restrict__ out,
                                             float* __restrict__ seen) {
    int gw = (blockIdx.x * blockDim.x + threadIdx.x) >> 5;
    int l  = threadIdx.x & 31;
    if (gw >= NSEG) return;
    int r0 = csr[gw], r1 = csr[gw + 1];
    int cnt = r1 - r0;
    float* op = out + (size_t)gw * 128;
    if (cnt <= 0) {
        *(float4*)&op[4 * l] = make_float4(0.f, 0.f, 0.f, 0.f);
        if (seen && l == 0) seen[gw] = 0.f;
        return;
    }
    float pt0 = g_Pt[(size_t)gw*64 + l],       pt1 = g_Pt[(size_t)gw*64 + 32 + l];
    float4 pb4 = *(const float4*)&g_Pb[(size_t)gw * 128 + 4 * l];
    float cc  = g_c[gw];
    float s2a = g_s2[l], s2b = g_s2[32 + l];
    float t2a = g_t2[l], t2b = g_t2[32 + l];
    float inv = rsqrtf((float)cnt);

    float m = -INFINITY, d = 0.f;
    const unsigned FULL = 0xffffffffu;
    for (int v = r0; v < r1; v++) {
        const __half* zr = g_z2 + (size_t)v * 64;
        float ha = fmaxf(fmaf(__half2float(zr[l]),      s2a, t2a), 0.f);
        float hb = fmaxf(fmaf(__half2float(zr[32 + l]), s2b, t2b), 0.f);
        float4 x4 = *(const float4*)(x_mod + (size_t)v * 128 + 4 * l);
        float part = ha * pt0 + hb * pt1
                   + x4.x * pb4.x + x4.y * pb4.y + x4.z * pb4.z + x4.w * pb4.w;
#pragma unroll
        for (int o = 16; o > 0; o >>= 1) part += __shfl_xor_sync(FULL, part, o);
        float X = part + cc;
        if (l == 0) g_X[v] = X;
        if (X > m) { d = d * __expf((m - X) * inv) + 1.f; m = X; }
        else       { d += __expf((X - m) * inv); }
    }
    __threadfence_block();
    __syncwarp();

    float scale = tanhf(fmaxf(m, 0.f)) / (d + 1e-12f);   // gate / denom
    float4 p4 = make_float4(-INFINITY, -INFINITY, -INFINITY, -INFINITY);
    for (int v = r0; v < r1; v++) {
        float a = __expf((g_X[v] - m) * inv);            // broadcast load
        float4 x4 = *(const float4*)(x_mod + (size_t)v * 128 + 4 * l);
        p4.x = fmaxf(p4.x, x4.x * a);
        p4.y = fmaxf(p4.y, x4.y * a);
        p4.z = fmaxf(p4.z, x4.z * a);
        p4.w = fmaxf(p4.w, x4.w * a);
    }
    *(float4*)&op[4 * l] = make_float4(p4.x * scale, p4.y * scale,
                                       p4.z * scale, p4.w * scale);
    if (seen && l == 0) seen[gw] = 1.f;
}

// ---------------- launch ----------------------------------------------------
extern "C" void kernel_launch(void* const* d_in, const int* in_sizes, int n_in,
                              void* d_out, int out_size) {
    const float* x_main = (const float*)d_in[0];
    const float* x_mod  = (const float*)d_in[1];
    const float* x_proj = (const float*)d_in[2];
    const int*   csr    = (const int*)  d_in[3];
    const float* Wq     = (const float*)d_in[4];
    const float* bq     = (const float*)d_in[5];
    const float* W1     = (const float*)d_in[6];
    const float* b1     = (const float*)d_in[7];
    const float* g1     = (const float*)d_in[8];
    const float* beta1  = (const float*)d_in[9];
    const float* W2     = (const float*)d_in[10];
    const float* b2     = (const float*)d_in[11];
    const float* g2     = (const float*)d_in[12];
    const float* beta2  = (const float*)d_in[13];
    const float* Wk     = (const float*)d_in[14];
    const float* bk     = (const float*)d_in[15];

    float* out  = (float*)d_out;
    float* seen = (out_size >= NSEG * 129) ? out + (size_t)NSEG * 128 : nullptr;

    const int MLP2_SMEM = (64 * 264 + 2048 + 4096 + 256) * 4;   // 93184 B
    cudaFuncSetAttribute(k_mlp2, cudaFuncAttributeMaxDynamicSharedMemorySize, MLP2_SMEM);

    k_init  <<<1, 256>>>();
    k_gram2 <<<(VROWS + 1023) / 1024, 256>>>(x_proj);
    k_fing  <<<1, 64>>>(W1, b1, g1, beta1);
    k_mlp2  <<<(VROWS + 255) / 256, 256, MLP2_SMEM>>>(x_proj, W1, b1, W2, b2);
    k_fin2  <<<1, 64>>>(g2, beta2);
    k_q     <<<(NSEG + 63) / 64, 64>>>(x_main, Wq, bq);
    k_p     <<<(NSEG + 511) / 512, 128>>>(Wk, bk);
    k_seg   <<<(NSEG + 7) / 8, 256>>>(x_mod, csr, out, seen);
}

// round 15
// speedup vs baseline: 1.4665x; 1.4665x over previous
#include <cuda_runtime.h>
#include <cuda_fp16.h>
#include <math.h>

#define NSEG  125000
#define VROWS 1000000

typedef unsigned long long u64;

// ---------------- packed f32x2 helpers (sm_100+) ----------------------------
__device__ __forceinline__ u64 pack2(float x) {
    u64 r; unsigned xi = __float_as_uint(x);
    asm("mov.b64 %0, {%1, %1};" : "=l"(r) : "r"(xi));
    return r;
}
__device__ __forceinline__ void unpack2(u64 v, float& a, float& b) {
    unsigned lo, hi;
    asm("mov.b64 {%0, %1}, %2;" : "=r"(lo), "=r"(hi) : "l"(v));
    a = __uint_as_float(lo); b = __uint_as_float(hi);
}
__device__ __forceinline__ void ffma2(u64& acc, u64 a, u64 b) {
    asm("fma.rn.f32x2 %0, %1, %2, %0;" : "+l"(acc) : "l"(a), "l"(b));
}

// ---------------- scratch (device globals; no allocation allowed) ----------
static __device__ __half g_z2[(size_t)VROWS * 64];  // z2 pre-BN activations (fp16)
static __device__ float g_q [(size_t)NSEG * 64];    // per-segment query
static __device__ float g_Pt[(size_t)NSEG * 64];    // Wk_top @ q   (h2 part)
static __device__ float g_Pb[(size_t)NSEG * 128];   // Wk_bot @ q   (x_mod part)
static __device__ float g_c [NSEG];                 // bk . q
static __device__ float g_X [VROWS];                // per-row scores
static __device__ float g_gram[1024];               // X^T X  (32x32)
static __device__ float g_sx[32];                   // sum of x_proj rows
static __device__ float g_stats2[128];              // sum(64) | sumsq(64)
static __device__ float g_s1[64], g_t1[64], g_s2[64], g_t2[64];

// ---------------- init: zero accumulators ----------------------------------
__global__ void k_init() {
    int t = threadIdx.x;
    for (int i = t; i < 1024; i += 256) g_gram[i] = 0.f;
    if (t < 32)  g_sx[t] = 0.f;
    if (t < 128) g_stats2[t] = 0.f;
}

// ---------------- Gram pass (syrk in shared, NO shuffles) ------------------
// 1024 rows/block in 8 stages of 128. Thread t owns Gram entries 4t..4t+3.
__global__ void __launch_bounds__(256) k_gram2(const float* __restrict__ xp) {
    __shared__ __align__(16) float sX[128 * 36];   // pad 36: LDS.128-aligned rows
    int t = threadIdx.x;
    int base = blockIdx.x * 1024;
    int i0 = (4 * t) >> 5;        // Gram row
    int j0 = (4 * t) & 31;        // Gram col (multiple of 4)
    float acc0 = 0.f, acc1 = 0.f, acc2 = 0.f, acc3 = 0.f;
    float sxl = 0.f;

    for (int stage = 0; stage < 8; stage++) {
        int rbase = base + stage * 128;
        int nr = VROWS - rbase;
        if (nr <= 0) break;
        if (nr > 128) nr = 128;
        __syncthreads();                        // previous-stage reads done
        const float4* xg = (const float4*)(xp + (size_t)rbase * 32);
        for (int idx = t; idx < nr * 8; idx += 256) {
            float4 v = xg[idx];
            int r = idx >> 3, c = (idx & 7) << 2;
            float* d = &sX[r * 36 + c];
            d[0] = v.x; d[1] = v.y; d[2] = v.z; d[3] = v.w;
        }
        __syncthreads();
#pragma unroll 4
        for (int r = 0; r < nr; r++) {
            float  xi = sX[r * 36 + i0];                    // broadcast
            float4 xj = *(const float4*)&sX[r * 36 + j0];   // LDS.128
            acc0 = fmaf(xi, xj.x, acc0);
            acc1 = fmaf(xi, xj.y, acc1);
            acc2 = fmaf(xi, xj.z, acc2);
            acc3 = fmaf(xi, xj.w, acc3);
        }
        if (t < 32) {                                       // column sums
            for (int r = 0; r < nr; r++) sxl += sX[r * 36 + t];
        }
    }
    atomicAdd(&g_gram[4 * t + 0], acc0);
    atomicAdd(&g_gram[4 * t + 1], acc1);
    atomicAdd(&g_gram[4 * t + 2], acc2);
    atomicAdd(&g_gram[4 * t + 3], acc3);
    if (t < 32) atomicAdd(&g_sx[t], sxl);
}

// ---------------- finalize BN1 from Gram -----------------------------------
__global__ void k_fing(const float* __restrict__ W1, const float* __restrict__ b1,
                       const float* __restrict__ g1, const float* __restrict__ beta1) {
    __shared__ float sG[1024];
    __shared__ float sx[32];
    int t = threadIdx.x;                 // 64 threads, one per channel
    for (int i = t; i < 1024; i += 64) sG[i] = g_gram[i];
    if (t < 32) sx[t] = g_sx[t];
    __syncthreads();
    float w[32];
#pragma unroll
    for (int i = 0; i < 32; i++) w[i] = W1[i * 64 + t];
    float wgw = 0.f, wsx = 0.f;
    for (int i = 0; i < 32; i++) {
        float ti = 0.f;
#pragma unroll
        for (int k = 0; k < 32; k++) ti = fmaf(sG[i * 32 + k], w[k], ti);
        wgw = fmaf(w[i], ti, wgw);
        wsx = fmaf(w[i], sx[i], wsx);
    }
    float bj = b1[t];
    const float invV = 1.f / (float)VROWS;
    float mu  = wsx * invV + bj;
    float ez2 = (wgw + 2.f * bj * wsx) * invV + bj * bj;
    float var = ez2 - mu * mu;
    float s   = g1[t] * rsqrtf(var + 1e-5f);
    g_s1[t] = s;
    g_t1[t] = beta1[t] - mu * s;
}

// ---------------- mlp2: tiled GEMM1 -> BN1/ReLU -> tiled GEMM2 -------------
// 256 rows/block, 256 threads, 8 rows x 8 cols per thread. z2 stored fp16.
__global__ void __launch_bounds__(256, 2) k_mlp2(const float* __restrict__ xp,
                                                 const float* __restrict__ W1,
                                                 const float* __restrict__ b1,
                                                 const float* __restrict__ W2,
                                                 const float* __restrict__ b2) {
    extern __shared__ float sm[];
    float* sB   = sm;                    // 64 x 264 (x^T rows 0..31, then h1^T rows 0..63)
    float* sW1  = sm + 64 * 264;         // 2048
    float* sW2  = sW1 + 2048;            // 4096
    float* sS1  = sW2 + 4096;            // 64
    float* sT1  = sS1 + 64;              // 64
    float* sSum = sT1 + 64;              // 64
    float* sSq  = sSum + 64;             // 64

    int t = threadIdx.x;
    int base = blockIdx.x * 256;
    int nrows = VROWS - base; if (nrows > 256) nrows = 256;
    int cg = t & 7, rg = t >> 3;

    for (int i = t; i < 512;  i += 256) ((float4*)sW1)[i] = ((const float4*)W1)[i];
    for (int i = t; i < 1024; i += 256) ((float4*)sW2)[i] = ((const float4*)W2)[i];
    if (t < 64) { sS1[t] = g_s1[t]; sT1[t] = g_t1[t]; sSum[t] = 0.f; sSq[t] = 0.f; }

    // stage x transposed: sB[c][r] = x[base+r][c] (zero-fill past nrows)
    {
        const float4* xg = (const float4*)(xp + (size_t)base * 32);
        for (int i = t; i < 2048; i += 256) {
            int r = i >> 3, c4 = (i & 7) << 2;
            float4 v = (r < nrows) ? xg[i] : make_float4(0.f, 0.f, 0.f, 0.f);
            sB[(c4 + 0) * 264 + r] = v.x;
            sB[(c4 + 1) * 264 + r] = v.y;
            sB[(c4 + 2) * 264 + r] = v.z;
            sB[(c4 + 3) * 264 + r] = v.w;
        }
    }
    __syncthreads();

    u64 acc[32];
    {
        const u64* bp = (const u64*)b1;
        u64 c0 = bp[cg * 4 + 0], c1 = bp[cg * 4 + 1], c2 = bp[cg * 4 + 2], c3 = bp[cg * 4 + 3];
#pragma unroll
        for (int r = 0; r < 8; r++) { acc[r*4+0]=c0; acc[r*4+1]=c1; acc[r*4+2]=c2; acc[r*4+3]=c3; }
    }
#pragma unroll 4
    for (int k = 0; k < 32; k++) {
        float4 xa = *(const float4*)&sB[k * 264 + rg * 8];
        float4 xb = *(const float4*)&sB[k * 264 + rg * 8 + 4];
        ulonglong2 wA = *(const ulonglong2*)&sW1[k * 64 + cg * 8];
        ulonglong2 wB = *(const ulonglong2*)&sW1[k * 64 + cg * 8 + 4];
        float xs[8] = {xa.x, xa.y, xa.z, xa.w, xb.x, xb.y, xb.z, xb.w};
#pragma unroll
        for (int r = 0; r < 8; r++) {
            u64 xx = pack2(xs[r]);
            ffma2(acc[r*4+0], xx, wA.x);
            ffma2(acc[r*4+1], xx, wA.y);
            ffma2(acc[r*4+2], xx, wB.x);
            ffma2(acc[r*4+3], xx, wB.y);
        }
    }
    __syncthreads();                      // all reads of x^T done

    // BN1 + ReLU -> h1^T into sB (rows = channels 0..63)
#pragma unroll
    for (int cp = 0; cp < 4; cp++) {
        int c0 = cg * 8 + cp * 2;
        float s0 = sS1[c0], t0 = sT1[c0], s1 = sS1[c0 + 1], t1 = sT1[c0 + 1];
        float h0[8], h1[8];
#pragma unroll
        for (int r = 0; r < 8; r++) {
            float a, b; unpack2(acc[r*4+cp], a, b);
            h0[r] = fmaxf(fmaf(a, s0, t0), 0.f);
            h1[r] = fmaxf(fmaf(b, s1, t1), 0.f);
        }
        *(float4*)&sB[c0 * 264 + rg * 8]           = make_float4(h0[0], h0[1], h0[2], h0[3]);
        *(float4*)&sB[c0 * 264 + rg * 8 + 4]       = make_float4(h0[4], h0[5], h0[6], h0[7]);
        *(float4*)&sB[(c0 + 1) * 264 + rg * 8]     = make_float4(h1[0], h1[1], h1[2], h1[3]);
        *(float4*)&sB[(c0 + 1) * 264 + rg * 8 + 4] = make_float4(h1[4], h1[5], h1[6], h1[7]);
    }
    __syncthreads();

    {
        const u64* bp = (const u64*)b2;
        u64 c0 = bp[cg * 4 + 0], c1 = bp[cg * 4 + 1], c2 = bp[cg * 4 + 2], c3 = bp[cg * 4 + 3];
#pragma unroll
        for (int r = 0; r < 8; r++) { acc[r*4+0]=c0; acc[r*4+1]=c1; acc[r*4+2]=c2; acc[r*4+3]=c3; }
    }
#pragma unroll 4
    for (int k = 0; k < 64; k++) {
        float4 xa = *(const float4*)&sB[k * 264 + rg * 8];
        float4 xb = *(const float4*)&sB[k * 264 + rg * 8 + 4];
        ulonglong2 wA = *(const ulonglong2*)&sW2[k * 64 + cg * 8];
        ulonglong2 wB = *(const ulonglong2*)&sW2[k * 64 + cg * 8 + 4];
        float xs[8] = {xa.x, xa.y, xa.z, xa.w, xb.x, xb.y, xb.z, xb.w};
#pragma unroll
        for (int r = 0; r < 8; r++) {
            u64 xx = pack2(xs[r]);
            ffma2(acc[r*4+0], xx, wA.x);
            ffma2(acc[r*4+1], xx, wA.y);
            ffma2(acc[r*4+2], xx, wB.x);
            ffma2(acc[r*4+3], xx, wB.y);
        }
    }

    // store z2 (fp16) + accumulate BN2 stats (f32)
    float ss[8], qq[8];
#pragma unroll
    for (int i = 0; i < 8; i++) { ss[i] = 0.f; qq[i] = 0.f; }
#pragma unroll
    for (int r = 0; r < 8; r++) {
        int row = rg * 8 + r;
        if (row < nrows) {
            float a0, b0, a1, b1v, a2, b2v, a3, b3;
            unpack2(acc[r*4+0], a0, b0);
            unpack2(acc[r*4+1], a1, b1v);
            unpack2(acc[r*4+2], a2, b2v);
            unpack2(acc[r*4+3], a3, b3);
            __half2 h0 = __floats2half2_rn(a0, b0);
            __half2 h1 = __floats2half2_rn(a1, b1v);
            __half2 h2 = __floats2half2_rn(a2, b2v);
            __half2 h3 = __floats2half2_rn(a3, b3);
            uint4 pk = make_uint4(*(unsigned*)&h0, *(unsigned*)&h1,
                                  *(unsigned*)&h2, *(unsigned*)&h3);
            *(uint4*)(g_z2 + (size_t)(base + row) * 64 + cg * 8) = pk;
            ss[0] += a0; qq[0] += a0 * a0;  ss[1] += b0; qq[1] += b0 * b0;
            ss[2] += a1; qq[2] += a1 * a1;  ss[3] += b1v; qq[3] += b1v * b1v;
            ss[4] += a2; qq[4] += a2 * a2;  ss[5] += b2v; qq[5] += b2v * b2v;
            ss[6] += a3; qq[6] += a3 * a3;  ss[7] += b3; qq[7] += b3 * b3;
        }
    }
    const unsigned FULL = 0xffffffffu;
#pragma unroll
    for (int o = 8; o <= 16; o <<= 1) {
#pragma unroll
        for (int i = 0; i < 8; i++) {
            ss[i] += __shfl_xor_sync(FULL, ss[i], o);
            qq[i] += __shfl_xor_sync(FULL, qq[i], o);
        }
    }
    if ((t & 31) < 8) {                  // these lanes have lane == cg
#pragma unroll
        for (int c = 0; c < 8; c++) {
            atomicAdd(&sSum[cg * 8 + c], ss[c]);
            atomicAdd(&sSq [cg * 8 + c], qq[c]);
        }
    }
    __syncthreads();
    if (t < 64) {
        atomicAdd(&g_stats2[t],      sSum[t]);
        atomicAdd(&g_stats2[64 + t], sSq[t]);
    }
}

// ---------------- finalize BN2 ---------------------------------------------
__global__ void k_fin2(const float* __restrict__ g, const float* __restrict__ beta) {
    int c = threadIdx.x;
    if (c >= 64) return;
    float mu  = g_stats2[c] * (1.f / (float)VROWS);
    float var = g_stats2[64 + c] * (1.f / (float)VROWS) - mu * mu;
    float s   = g[c] * rsqrtf(var + 1e-5f);
    g_s2[c] = s;
    g_t2[c] = beta[c] - mu * s;
}

// ---------------- per-segment query q = x_main@Wq + bq ---------------------
__global__ void __launch_bounds__(64) k_q(const float* __restrict__ xm,
                                          const float* __restrict__ Wq,
                                          const float* __restrict__ bq) {
    __shared__ __align__(16) float sX[64 * 65];
    __shared__ __align__(16) float sW[4096];
    int t = threadIdx.x;
    int base = blockIdx.x * 64;
    int nrows = min(64, NSEG - base);

    for (int i = t; i < 1024; i += 64)
        ((float4*)sW)[i] = ((const float4*)Wq)[i];
    const float4* xg = (const float4*)(xm + (size_t)base * 64);
    for (int i = t; i < nrows * 16; i += 64) {
        float4 v = xg[i];
        int r = i >> 4, c = (i & 15) << 2;
        float* d = &sX[r * 65 + c];
        d[0] = v.x; d[1] = v.y; d[2] = v.z; d[3] = v.w;
    }
    __syncthreads();

    if (t >= nrows) return;
    int n = base + t;
    u64 acc[32];
    const u64* bp = (const u64*)bq;
#pragma unroll
    for (int j = 0; j < 32; j++) acc[j] = bp[j];
#pragma unroll 8
    for (int k = 0; k < 64; k++) {
        u64 xx = pack2(sX[t * 65 + k]);
        const ulonglong2* wr = (const ulonglong2*)(sW + k * 64);
#pragma unroll
        for (int jo = 0; jo < 16; jo++) {
            ulonglong2 w = wr[jo];
            ffma2(acc[2 * jo],     xx, w.x);
            ffma2(acc[2 * jo + 1], xx, w.y);
        }
    }
    ulonglong2* qo = (ulonglong2*)(g_q + (size_t)n * 64);
#pragma unroll
    for (int jo = 0; jo < 16; jo++)
        qo[jo] = make_ulonglong2(acc[2 * jo], acc[2 * jo + 1]);
}

// ---------------- P = Wk @ q (192), c = bk.q ; 4 segments/thread -----------
__global__ void __launch_bounds__(128) k_p(const float* __restrict__ Wk,
                                           const float* __restrict__ bk) {
    __shared__ float sW[12288];          // 48 KB: Wk row-major [192,64]
    int t = threadIdx.x;
    for (int i = t; i < 3072; i += 128) ((float4*)sW)[i] = ((const float4*)Wk)[i];
    __syncthreads();

    int n0 = blockIdx.x * 512 + t;
    int n1 = n0 + 128, n2 = n0 + 256, n3 = n0 + 384;
    bool v0 = n0 < NSEG, v1 = n1 < NSEG, v2 = n2 < NSEG, v3 = n3 < NSEG;
    const ulonglong2* q0 = (const ulonglong2*)(g_q + (size_t)(v0 ? n0 : 0) * 64);
    const ulonglong2* q1 = (const ulonglong2*)(g_q + (size_t)(v1 ? n1 : 0) * 64);
    const ulonglong2* q2 = (const ulonglong2*)(g_q + (size_t)(v2 ? n2 : 0) * 64);
    const ulonglong2* q3 = (const ulonglong2*)(g_q + (size_t)(v3 ? n3 : 0) * 64);

    // c = bk . q
    {
        const float4* bkr = (const float4*)bk;
        float c0 = 0.f, c1 = 0.f, c2 = 0.f, c3 = 0.f;
#pragma unroll
        for (int jo = 0; jo < 16; jo++) {
            float4 b4 = bkr[jo];
            float4 qa = ((const float4*)q0)[jo];
            float4 qb = ((const float4*)q1)[jo];
            float4 qc = ((const float4*)q2)[jo];
            float4 qd = ((const float4*)q3)[jo];
            c0 += qa.x * b4.x + qa.y * b4.y + qa.z * b4.z + qa.w * b4.w;
            c1 += qb.x * b4.x + qb.y * b4.y + qb.z * b4.z + qb.w * b4.w;
            c2 += qc.x * b4.x + qc.y * b4.y + qc.z * b4.z + qc.w * b4.w;
            c3 += qd.x * b4.x + qd.y * b4.y + qd.z * b4.z + qd.w * b4.w;
        }
        if (v0) g_c[n0] = c0;
        if (v1) g_c[n1] = c1;
        if (v2) g_c[n2] = c2;
        if (v3) g_c[n3] = c3;
    }

    for (int chunk = 0; chunk < 24; chunk++) {
        u64 a0[8], a1[8], a2[8], a3[8];
#pragma unroll
        for (int i = 0; i < 8; i++) { a0[i] = 0ull; a1[i] = 0ull; a2[i] = 0ull; a3[i] = 0ull; }
        for (int jo = 0; jo < 16; jo++) {
            ulonglong2 qa = q0[jo];     // L1 hit after first chunk
            ulonglong2 qb = q1[jo];
            ulonglong2 qc = q2[jo];
            ulonglong2 qd = q3[jo];
#pragma unroll
            for (int i = 0; i < 8; i++) {
                ulonglong2 w = ((const ulonglong2*)sW)[(chunk * 8 + i) * 16 + jo];
                ffma2(a0[i], qa.x, w.x); ffma2(a0[i], qa.y, w.y);
                ffma2(a1[i], qb.x, w.x); ffma2(a1[i], qb.y, w.y);
                ffma2(a2[i], qc.x, w.x); ffma2(a2[i], qc.y, w.y);
                ffma2(a3[i], qd.x, w.x); ffma2(a3[i], qd.y, w.y);
            }
        }
        int o = chunk * 8;
        float *d0, *d1, *d2, *d3;
        if (o < 64) { d0 = g_Pt + (size_t)n0 * 64 + o;  d1 = g_Pt + (size_t)n1 * 64 + o;
                      d2 = g_Pt + (size_t)n2 * 64 + o;  d3 = g_Pt + (size_t)n3 * 64 + o; }
        else        { d0 = g_Pb + (size_t)n0 * 128 + (o - 64); d1 = g_Pb + (size_t)n1 * 128 + (o - 64);
                      d2 = g_Pb + (size_t)n2 * 128 + (o - 64); d3 = g_Pb + (size_t)n3 * 128 + (o - 64); }
#pragma unroll
        for (int i = 0; i < 8; i++) {
            float lo, hi;
            if (v0) { unpack2(a0[i], lo, hi); d0[i] = lo + hi; }
            if (v1) { unpack2(a1[i], lo, hi); d1[i] = lo + hi; }
            if (v2) { unpack2(a2[i], lo, hi); d2[i] = lo + hi; }
            if (v3) { unpack2(a3[i], lo, hi); d3[i] = lo + hi; }
        }
    }
}

// ---------------- warp-per-segment, two-pass; float4 x_mod path ------------
// Lane l owns x_mod channels 4l..4l+3 (one float4). Same bytes, same chains
// as the R12 kernel — strictly fewer instructions.
__global__ void __launch_bounds__(256) k_seg(const float* __restrict__ x_mod,
                                             const int* __restrict__ csr,
                                             float* __restrict__ out,
                                             float* __restrict__ seen) {
    int gw = (blockIdx.x * blockDim.x + threadIdx.x) >> 5;
    int l  = threadIdx.x & 31;
    if (gw >= NSEG) return;
    int r0 = csr[gw], r1 = csr[gw + 1];
    int cnt = r1 - r0;
    float* op = out + (size_t)gw * 128;
    if (cnt <= 0) {
        *(float4*)&op[4 * l] = make_float4(0.f, 0.f, 0.f, 0.f);
        if (seen && l == 0) seen[gw] = 0.f;
        return;
    }
    float pt0 = g_Pt[(size_t)gw*64 + l],       pt1 = g_Pt[(size_t)gw*64 + 32 + l];
    float4 pb4 = *(const float4*)&g_Pb[(size_t)gw * 128 + 4 * l];
    float cc  = g_c[gw];
    float s2a = g_s2[l], s2b = g_s2[32 + l];
    float t2a = g_t2[l], t2b = g_t2[32 + l];
    float inv = rsqrtf((float)cnt);

    float m = -INFINITY, d = 0.f;
    const unsigned FULL = 0xffffffffu;
    for (int v = r0; v < r1; v++) {
        const __half* zr = g_z2 + (size_t)v * 64;
        float ha = fmaxf(fmaf(__half2float(zr[l]),      s2a, t2a), 0.f);
        float hb = fmaxf(fmaf(__half2float(zr[32 + l]), s2b, t2b), 0.f);
        float4 x4 = *(const float4*)(x_mod + (size_t)v * 128 + 4 * l);
        float part = ha * pt0 + hb * pt1
                   + x4.x * pb4.x + x4.y * pb4.y + x4.z * pb4.z + x4.w * pb4.w;
#pragma unroll
        for (int o = 16; o > 0; o >>= 1) part += __shfl_xor_sync(FULL, part, o);
        float X = part + cc;
        if (l == 0) g_X[v] = X;
        if (X > m) { d = d * __expf((m - X) * inv) + 1.f; m = X; }
        else       { d += __expf((X - m) * inv); }
    }
    __threadfence_block();
    __syncwarp();

    float scale = tanhf(fmaxf(m, 0.f)) / (d + 1e-12f);   // gate / denom
    float4 p4 = make_float4(-INFINITY, -INFINITY, -INFINITY, -INFINITY);
    for (int v = r0; v < r1; v++) {
        float a = __expf((g_X[v] - m) * inv);            // broadcast load
        float4 x4 = *(const float4*)(x_mod + (size_t)v * 128 + 4 * l);
        p4.x = fmaxf(p4.x, x4.x * a);
        p4.y = fmaxf(p4.y, x4.y * a);
        p4.z = fmaxf(p4.z, x4.z * a);
        p4.w = fmaxf(p4.w, x4.w * a);
    }
    *(float4*)&op[4 * l] = make_float4(p4.x * scale, p4.y * scale,
                                       p4.z * scale, p4.w * scale);
    if (seen && l == 0) seen[gw] = 1.f;
}

// ---------------- launch ----------------------------------------------------
extern "C" void kernel_launch(void* const* d_in, const int* in_sizes, int n_in,
                              void* d_out, int out_size) {
    const float* x_main = (const float*)d_in[0];
    const float* x_mod  = (const float*)d_in[1];
    const float* x_proj = (const float*)d_in[2];
    const int*   csr    = (const int*)  d_in[3];
    const float* Wq     = (const float*)d_in[4];
    const float* bq     = (const float*)d_in[5];
    const float* W1     = (const float*)d_in[6];
    const float* b1     = (const float*)d_in[7];
    const float* g1     = (const float*)d_in[8];
    const float* beta1  = (const float*)d_in[9];
    const float* W2     = (const float*)d_in[10];
    const float* b2     = (const float*)d_in[11];
    const float* g2     = (const float*)d_in[12];
    const float* beta2  = (const float*)d_in[13];
    const float* Wk     = (const float*)d_in[14];
    const float* bk     = (const float*)d_in[15];

    float* out  = (float*)d_out;
    float* seen = (out_size >= NSEG * 129) ? out + (size_t)NSEG * 128 : nullptr;

    const int MLP2_SMEM = (64 * 264 + 2048 + 4096 + 256) * 4;   // 93184 B
    cudaFuncSetAttribute(k_mlp2, cudaFuncAttributeMaxDynamicSharedMemorySize, MLP2_SMEM);

    k_init  <<<1, 256>>>();
    k_gram2 <<<(VROWS + 1023) / 1024, 256>>>(x_proj);
    k_fing  <<<1, 64>>>(W1, b1, g1, beta1);
    k_mlp2  <<<(VROWS + 255) / 256, 256, MLP2_SMEM>>>(x_proj, W1, b1, W2, b2);
    k_fin2  <<<1, 64>>>(g2, beta2);
    k_q     <<<(NSEG + 63) / 64, 64>>>(x_main, Wq, bq);
    k_p     <<<(NSEG + 511) / 512, 128>>>(Wk, bk);
    k_seg   <<<(NSEG + 7) / 8, 256>>>(x_mod, csr, out, seen);
}

// round 16
// speedup vs baseline: 1.5497x; 1.0567x over previous
#include <cuda_runtime.h>
#include <cuda_fp16.h>
#include <math.h>

#define NSEG  125000
#define VROWS 1000000

typedef unsigned long long u64;

// ---------------- packed f32x2 helpers (sm_100+) ----------------------------
__device__ __forceinline__ u64 pack2(float x) {
    u64 r; unsigned xi = __float_as_uint(x);
    asm("mov.b64 %0, {%1, %1};" : "=l"(r) : "r"(xi));
    return r;
}
__device__ __forceinline__ void unpack2(u64 v, float& a, float& b) {
    unsigned lo, hi;
    asm("mov.b64 {%0, %1}, %2;" : "=r"(lo), "=r"(hi) : "l"(v));
    a = __uint_as_float(lo); b = __uint_as_float(hi);
}
__device__ __forceinline__ void ffma2(u64& acc, u64 a, u64 b) {
    asm("fma.rn.f32x2 %0, %1, %2, %0;" : "+l"(acc) : "l"(a), "l"(b));
}

// ---------------- scratch (device globals; no allocation allowed) ----------
static __device__ __half g_z2[(size_t)VROWS * 64];  // z2 pre-BN activations (fp16)
static __device__ float g_q [(size_t)NSEG * 64];    // per-segment query
static __device__ float g_Pt[(size_t)NSEG * 64];    // Wk_top @ q   (h2 part)
static __device__ float g_Pb[(size_t)NSEG * 128];   // Wk_bot @ q   (x_mod part)
static __device__ float g_c [NSEG];                 // bk . q
static __device__ float g_X [VROWS];                // per-row scores
static __device__ float g_gram[1024];               // X^T X  (32x32)
static __device__ float g_sx[32];                   // sum of x_proj rows
static __device__ float g_stats2[128];              // sum(64) | sumsq(64)
static __device__ float g_s1[64], g_t1[64], g_s2[64], g_t2[64];

// ---------------- init: zero accumulators ----------------------------------
__global__ void k_init() {
    int t = threadIdx.x;
    for (int i = t; i < 1024; i += 256) g_gram[i] = 0.f;
    if (t < 32)  g_sx[t] = 0.f;
    if (t < 128) g_stats2[t] = 0.f;
}

// ---------------- Gram pass (syrk in shared, NO shuffles) ------------------
// 1024 rows/block in 8 stages of 128. Thread t owns Gram entries 4t..4t+3.
__global__ void __launch_bounds__(256) k_gram2(const float* __restrict__ xp) {
    __shared__ __align__(16) float sX[128 * 36];   // pad 36: LDS.128-aligned rows
    int t = threadIdx.x;
    int base = blockIdx.x * 1024;
    int i0 = (4 * t) >> 5;        // Gram row
    int j0 = (4 * t) & 31;        // Gram col (multiple of 4)
    float acc0 = 0.f, acc1 = 0.f, acc2 = 0.f, acc3 = 0.f;
    float sxl = 0.f;

    for (int stage = 0; stage < 8; stage++) {
        int rbase = base + stage * 128;
        int nr = VROWS - rbase;
        if (nr <= 0) break;
        if (nr > 128) nr = 128;
        __syncthreads();                        // previous-stage reads done
        const float4* xg = (const float4*)(xp + (size_t)rbase * 32);
        for (int idx = t; idx < nr * 8; idx += 256) {
            float4 v = xg[idx];
            int r = idx >> 3, c = (idx & 7) << 2;
            float* d = &sX[r * 36 + c];
            d[0] = v.x; d[1] = v.y; d[2] = v.z; d[3] = v.w;
        }
        __syncthreads();
#pragma unroll 4
        for (int r = 0; r < nr; r++) {
            float  xi = sX[r * 36 + i0];                    // broadcast
            float4 xj = *(const float4*)&sX[r * 36 + j0];   // LDS.128
            acc0 = fmaf(xi, xj.x, acc0);
            acc1 = fmaf(xi, xj.y, acc1);
            acc2 = fmaf(xi, xj.z, acc2);
            acc3 = fmaf(xi, xj.w, acc3);
        }
        if (t < 32) {                                       // column sums
            for (int r = 0; r < nr; r++) sxl += sX[r * 36 + t];
        }
    }
    atomicAdd(&g_gram[4 * t + 0], acc0);
    atomicAdd(&g_gram[4 * t + 1], acc1);
    atomicAdd(&g_gram[4 * t + 2], acc2);
    atomicAdd(&g_gram[4 * t + 3], acc3);
    if (t < 32) atomicAdd(&g_sx[t], sxl);
}

// ---------------- finalize BN1 from Gram -----------------------------------
__global__ void k_fing(const float* __restrict__ W1, const float* __restrict__ b1,
                       const float* __restrict__ g1, const float* __restrict__ beta1) {
    __shared__ float sG[1024];
    __shared__ float sx[32];
    int t = threadIdx.x;                 // 64 threads, one per channel
    for (int i = t; i < 1024; i += 64) sG[i] = g_gram[i];
    if (t < 32) sx[t] = g_sx[t];
    __syncthreads();
    float w[32];
#pragma unroll
    for (int i = 0; i < 32; i++) w[i] = W1[i * 64 + t];
    float wgw = 0.f, wsx = 0.f;
    for (int i = 0; i < 32; i++) {
        float ti = 0.f;
#pragma unroll
        for (int k = 0; k < 32; k++) ti = fmaf(sG[i * 32 + k], w[k], ti);
        wgw = fmaf(w[i], ti, wgw);
        wsx = fmaf(w[i], sx[i], wsx);
    }
    float bj = b1[t];
    const float invV = 1.f / (float)VROWS;
    float mu  = wsx * invV + bj;
    float ez2 = (wgw + 2.f * bj * wsx) * invV + bj * bj;
    float var = ez2 - mu * mu;
    float s   = g1[t] * rsqrtf(var + 1e-5f);
    g_s1[t] = s;
    g_t1[t] = beta1[t] - mu * s;
}

// ---------------- mlp2: tiled GEMM1 -> BN1/ReLU -> tiled GEMM2 -------------
// 256 rows/block, 256 threads, 8 rows x 8 cols per thread. z2 stored fp16.
__global__ void __launch_bounds__(256, 2) k_mlp2(const float* __restrict__ xp,
                                                 const float* __restrict__ W1,
                                                 const float* __restrict__ b1,
                                                 const float* __restrict__ W2,
                                                 const float* __restrict__ b2) {
    extern __shared__ float sm[];
    float* sB   = sm;                    // 64 x 264 (x^T rows 0..31, then h1^T rows 0..63)
    float* sW1  = sm + 64 * 264;         // 2048
    float* sW2  = sW1 + 2048;            // 4096
    float* sS1  = sW2 + 4096;            // 64
    float* sT1  = sS1 + 64;              // 64
    float* sSum = sT1 + 64;              // 64
    float* sSq  = sSum + 64;             // 64

    int t = threadIdx.x;
    int base = blockIdx.x * 256;
    int nrows = VROWS - base; if (nrows > 256) nrows = 256;
    int cg = t & 7, rg = t >> 3;

    for (int i = t; i < 512;  i += 256) ((float4*)sW1)[i] = ((const float4*)W1)[i];
    for (int i = t; i < 1024; i += 256) ((float4*)sW2)[i] = ((const float4*)W2)[i];
    if (t < 64) { sS1[t] = g_s1[t]; sT1[t] = g_t1[t]; sSum[t] = 0.f; sSq[t] = 0.f; }

    // stage x transposed: sB[c][r] = x[base+r][c] (zero-fill past nrows)
    {
        const float4* xg = (const float4*)(xp + (size_t)base * 32);
        for (int i = t; i < 2048; i += 256) {
            int r = i >> 3, c4 = (i & 7) << 2;
            float4 v = (r < nrows) ? xg[i] : make_float4(0.f, 0.f, 0.f, 0.f);
            sB[(c4 + 0) * 264 + r] = v.x;
            sB[(c4 + 1) * 264 + r] = v.y;
            sB[(c4 + 2) * 264 + r] = v.z;
            sB[(c4 + 3) * 264 + r] = v.w;
        }
    }
    __syncthreads();

    u64 acc[32];
    {
        const u64* bp = (const u64*)b1;
        u64 c0 = bp[cg * 4 + 0], c1 = bp[cg * 4 + 1], c2 = bp[cg * 4 + 2], c3 = bp[cg * 4 + 3];
#pragma unroll
        for (int r = 0; r < 8; r++) { acc[r*4+0]=c0; acc[r*4+1]=c1; acc[r*4+2]=c2; acc[r*4+3]=c3; }
    }
#pragma unroll 4
    for (int k = 0; k < 32; k++) {
        float4 xa = *(const float4*)&sB[k * 264 + rg * 8];
        float4 xb = *(const float4*)&sB[k * 264 + rg * 8 + 4];
        ulonglong2 wA = *(const ulonglong2*)&sW1[k * 64 + cg * 8];
        ulonglong2 wB = *(const ulonglong2*)&sW1[k * 64 + cg * 8 + 4];
        float xs[8] = {xa.x, xa.y, xa.z, xa.w, xb.x, xb.y, xb.z, xb.w};
#pragma unroll
        for (int r = 0; r < 8; r++) {
            u64 xx = pack2(xs[r]);
            ffma2(acc[r*4+0], xx, wA.x);
            ffma2(acc[r*4+1], xx, wA.y);
            ffma2(acc[r*4+2], xx, wB.x);
            ffma2(acc[r*4+3], xx, wB.y);
        }
    }
    __syncthreads();                      // all reads of x^T done

    // BN1 + ReLU -> h1^T into sB (rows = channels 0..63)
#pragma unroll
    for (int cp = 0; cp < 4; cp++) {
        int c0 = cg * 8 + cp * 2;
        float s0 = sS1[c0], t0 = sT1[c0], s1 = sS1[c0 + 1], t1 = sT1[c0 + 1];
        float h0[8], h1[8];
#pragma unroll
        for (int r = 0; r < 8; r++) {
            float a, b; unpack2(acc[r*4+cp], a, b);
            h0[r] = fmaxf(fmaf(a, s0, t0), 0.f);
            h1[r] = fmaxf(fmaf(b, s1, t1), 0.f);
        }
        *(float4*)&sB[c0 * 264 + rg * 8]           = make_float4(h0[0], h0[1], h0[2], h0[3]);
        *(float4*)&sB[c0 * 264 + rg * 8 + 4]       = make_float4(h0[4], h0[5], h0[6], h0[7]);
        *(float4*)&sB[(c0 + 1) * 264 + rg * 8]     = make_float4(h1[0], h1[1], h1[2], h1[3]);
        *(float4*)&sB[(c0 + 1) * 264 + rg * 8 + 4] = make_float4(h1[4], h1[5], h1[6], h1[7]);
    }
    __syncthreads();

    {
        const u64* bp = (const u64*)b2;
        u64 c0 = bp[cg * 4 + 0], c1 = bp[cg * 4 + 1], c2 = bp[cg * 4 + 2], c3 = bp[cg * 4 + 3];
#pragma unroll
        for (int r = 0; r < 8; r++) { acc[r*4+0]=c0; acc[r*4+1]=c1; acc[r*4+2]=c2; acc[r*4+3]=c3; }
    }
#pragma unroll 4
    for (int k = 0; k < 64; k++) {
        float4 xa = *(const float4*)&sB[k * 264 + rg * 8];
        float4 xb = *(const float4*)&sB[k * 264 + rg * 8 + 4];
        ulonglong2 wA = *(const ulonglong2*)&sW2[k * 64 + cg * 8];
        ulonglong2 wB = *(const ulonglong2*)&sW2[k * 64 + cg * 8 + 4];
        float xs[8] = {xa.x, xa.y, xa.z, xa.w, xb.x, xb.y, xb.z, xb.w};
#pragma unroll
        for (int r = 0; r < 8; r++) {
            u64 xx = pack2(xs[r]);
            ffma2(acc[r*4+0], xx, wA.x);
            ffma2(acc[r*4+1], xx, wA.y);
            ffma2(acc[r*4+2], xx, wB.x);
            ffma2(acc[r*4+3], xx, wB.y);
        }
    }

    // store z2 (fp16) + accumulate BN2 stats (f32)
    float ss[8], qq[8];
#pragma unroll
    for (int i = 0; i < 8; i++) { ss[i] = 0.f; qq[i] = 0.f; }
#pragma unroll
    for (int r = 0; r < 8; r++) {
        int row = rg * 8 + r;
        if (row < nrows) {
            float a0, b0, a1, b1v, a2, b2v, a3, b3;
            unpack2(acc[r*4+0], a0, b0);
            unpack2(acc[r*4+1], a1, b1v);
            unpack2(acc[r*4+2], a2, b2v);
            unpack2(acc[r*4+3], a3, b3);
            __half2 h0 = __floats2half2_rn(a0, b0);
            __half2 h1 = __floats2half2_rn(a1, b1v);
            __half2 h2 = __floats2half2_rn(a2, b2v);
            __half2 h3 = __floats2half2_rn(a3, b3);
            uint4 pk = make_uint4(*(unsigned*)&h0, *(unsigned*)&h1,
                                  *(unsigned*)&h2, *(unsigned*)&h3);
            *(uint4*)(g_z2 + (size_t)(base + row) * 64 + cg * 8) = pk;
            ss[0] += a0; qq[0] += a0 * a0;  ss[1] += b0; qq[1] += b0 * b0;
            ss[2] += a1; qq[2] += a1 * a1;  ss[3] += b1v; qq[3] += b1v * b1v;
            ss[4] += a2; qq[4] += a2 * a2;  ss[5] += b2v; qq[5] += b2v * b2v;
            ss[6] += a3; qq[6] += a3 * a3;  ss[7] += b3; qq[7] += b3 * b3;
        }
    }
    const unsigned FULL = 0xffffffffu;
#pragma unroll
    for (int o = 8; o <= 16; o <<= 1) {
#pragma unroll
        for (int i = 0; i < 8; i++) {
            ss[i] += __shfl_xor_sync(FULL, ss[i], o);
            qq[i] += __shfl_xor_sync(FULL, qq[i], o);
        }
    }
    if ((t & 31) < 8) {                  // these lanes have lane == cg
#pragma unroll
        for (int c = 0; c < 8; c++) {
            atomicAdd(&sSum[cg * 8 + c], ss[c]);
            atomicAdd(&sSq [cg * 8 + c], qq[c]);
        }
    }
    __syncthreads();
    if (t < 64) {
        atomicAdd(&g_stats2[t],      sSum[t]);
        atomicAdd(&g_stats2[64 + t], sSq[t]);
    }
}

// ---------------- finalize BN2 ---------------------------------------------
__global__ void k_fin2(const float* __restrict__ g, const float* __restrict__ beta) {
    int c = threadIdx.x;
    if (c >= 64) return;
    float mu  = g_stats2[c] * (1.f / (float)VROWS);
    float var = g_stats2[64 + c] * (1.f / (float)VROWS) - mu * mu;
    float s   = g[c] * rsqrtf(var + 1e-5f);
    g_s2[c] = s;
    g_t2[c] = beta[c] - mu * s;
}

// ---------------- per-segment query q = x_main@Wq + bq ---------------------
__global__ void __launch_bounds__(64) k_q(const float* __restrict__ xm,
                                          const float* __restrict__ Wq,
                                          const float* __restrict__ bq) {
    __shared__ __align__(16) float sX[64 * 65];
    __shared__ __align__(16) float sW[4096];
    int t = threadIdx.x;
    int base = blockIdx.x * 64;
    int nrows = min(64, NSEG - base);

    for (int i = t; i < 1024; i += 64)
        ((float4*)sW)[i] = ((const float4*)Wq)[i];
    const float4* xg = (const float4*)(xm + (size_t)base * 64);
    for (int i = t; i < nrows * 16; i += 64) {
        float4 v = xg[i];
        int r = i >> 4, c = (i & 15) << 2;
        float* d = &sX[r * 65 + c];
        d[0] = v.x; d[1] = v.y; d[2] = v.z; d[3] = v.w;
    }
    __syncthreads();

    if (t >= nrows) return;
    int n = base + t;
    u64 acc[32];
    const u64* bp = (const u64*)bq;
#pragma unroll
    for (int j = 0; j < 32; j++) acc[j] = bp[j];
#pragma unroll 8
    for (int k = 0; k < 64; k++) {
        u64 xx = pack2(sX[t * 65 + k]);
        const ulonglong2* wr = (const ulonglong2*)(sW + k * 64);
#pragma unroll
        for (int jo = 0; jo < 16; jo++) {
            ulonglong2 w = wr[jo];
            ffma2(acc[2 * jo],     xx, w.x);
            ffma2(acc[2 * jo + 1], xx, w.y);
        }
    }
    ulonglong2* qo = (ulonglong2*)(g_q + (size_t)n * 64);
#pragma unroll
    for (int jo = 0; jo < 16; jo++)
        qo[jo] = make_ulonglong2(acc[2 * jo], acc[2 * jo + 1]);
}

// ---------------- P = Wk @ q (192), c = bk.q ; 4 segments/thread -----------
__global__ void __launch_bounds__(128) k_p(const float* __restrict__ Wk,
                                           const float* __restrict__ bk) {
    __shared__ float sW[12288];          // 48 KB: Wk row-major [192,64]
    int t = threadIdx.x;
    for (int i = t; i < 3072; i += 128) ((float4*)sW)[i] = ((const float4*)Wk)[i];
    __syncthreads();

    int n0 = blockIdx.x * 512 + t;
    int n1 = n0 + 128, n2 = n0 + 256, n3 = n0 + 384;
    bool v0 = n0 < NSEG, v1 = n1 < NSEG, v2 = n2 < NSEG, v3 = n3 < NSEG;
    const ulonglong2* q0 = (const ulonglong2*)(g_q + (size_t)(v0 ? n0 : 0) * 64);
    const ulonglong2* q1 = (const ulonglong2*)(g_q + (size_t)(v1 ? n1 : 0) * 64);
    const ulonglong2* q2 = (const ulonglong2*)(g_q + (size_t)(v2 ? n2 : 0) * 64);
    const ulonglong2* q3 = (const ulonglong2*)(g_q + (size_t)(v3 ? n3 : 0) * 64);

    // c = bk . q
    {
        const float4* bkr = (const float4*)bk;
        float c0 = 0.f, c1 = 0.f, c2 = 0.f, c3 = 0.f;
#pragma unroll
        for (int jo = 0; jo < 16; jo++) {
            float4 b4 = bkr[jo];
            float4 qa = ((const float4*)q0)[jo];
            float4 qb = ((const float4*)q1)[jo];
            float4 qc = ((const float4*)q2)[jo];
            float4 qd = ((const float4*)q3)[jo];
            c0 += qa.x * b4.x + qa.y * b4.y + qa.z * b4.z + qa.w * b4.w;
            c1 += qb.x * b4.x + qb.y * b4.y + qb.z * b4.z + qb.w * b4.w;
            c2 += qc.x * b4.x + qc.y * b4.y + qc.z * b4.z + qc.w * b4.w;
            c3 += qd.x * b4.x + qd.y * b4.y + qd.z * b4.z + qd.w * b4.w;
        }
        if (v0) g_c[n0] = c0;
        if (v1) g_c[n1] = c1;
        if (v2) g_c[n2] = c2;
        if (v3) g_c[n3] = c3;
    }

    for (int chunk = 0; chunk < 24; chunk++) {
        u64 a0[8], a1[8], a2[8], a3[8];
#pragma unroll
        for (int i = 0; i < 8; i++) { a0[i] = 0ull; a1[i] = 0ull; a2[i] = 0ull; a3[i] = 0ull; }
        for (int jo = 0; jo < 16; jo++) {
            ulonglong2 qa = q0[jo];     // L1 hit after first chunk
            ulonglong2 qb = q1[jo];
            ulonglong2 qc = q2[jo];
            ulonglong2 qd = q3[jo];
#pragma unroll
            for (int i = 0; i < 8; i++) {
                ulonglong2 w = ((const ulonglong2*)sW)[(chunk * 8 + i) * 16 + jo];
                ffma2(a0[i], qa.x, w.x); ffma2(a0[i], qa.y, w.y);
                ffma2(a1[i], qb.x, w.x); ffma2(a1[i], qb.y, w.y);
                ffma2(a2[i], qc.x, w.x); ffma2(a2[i], qc.y, w.y);
                ffma2(a3[i], qd.x, w.x); ffma2(a3[i], qd.y, w.y);
            }
        }
        int o = chunk * 8;
        float *d0, *d1, *d2, *d3;
        if (o < 64) { d0 = g_Pt + (size_t)n0 * 64 + o;  d1 = g_Pt + (size_t)n1 * 64 + o;
                      d2 = g_Pt + (size_t)n2 * 64 + o;  d3 = g_Pt + (size_t)n3 * 64 + o; }
        else        { d0 = g_Pb + (size_t)n0 * 128 + (o - 64); d1 = g_Pb + (size_t)n1 * 128 + (o - 64);
                      d2 = g_Pb + (size_t)n2 * 128 + (o - 64); d3 = g_Pb + (size_t)n3 * 128 + (o - 64); }
#pragma unroll
        for (int i = 0; i < 8; i++) {
            float lo, hi;
            if (v0) { unpack2(a0[i], lo, hi); d0[i] = lo + hi; }
            if (v1) { unpack2(a1[i], lo, hi); d1[i] = lo + hi; }
            if (v2) { unpack2(a2[i], lo, hi); d2[i] = lo + hi; }
            if (v3) { unpack2(a3[i], lo, hi); d3[i] = lo + hi; }
        }
    }
}

// ---------------- warp-per-segment, two-pass; max-only pass 1 --------------
// Pass 1: scores + segment max (no exp on the chain). Pass 2: denominator
// and weighted max-pool together (exp off-chain); scale = gate/denom applied
// at the store — valid since max(x*e)/d == max(x*e/d) for constant d>0.
__global__ void __launch_bounds__(256) k_seg(const float* __restrict__ x_mod,
                                             const int* __restrict__ csr,
                                             float* __restrict__ out,
                                             float* __restrict__ seen) {
    int gw = (blockIdx.x * blockDim.x + threadIdx.x) >> 5;
    int l  = threadIdx.x & 31;
    if (gw >= NSEG) return;
    int r0 = csr[gw], r1 = csr[gw + 1];
    int cnt = r1 - r0;
    float* op = out + (size_t)gw * 128;
    if (cnt <= 0) {
        *(float4*)&op[4 * l] = make_float4(0.f, 0.f, 0.f, 0.f);
        if (seen && l == 0) seen[gw] = 0.f;
        return;
    }
    float pt0 = g_Pt[(size_t)gw*64 + l],       pt1 = g_Pt[(size_t)gw*64 + 32 + l];
    float4 pb4 = *(const float4*)&g_Pb[(size_t)gw * 128 + 4 * l];
    float cc  = g_c[gw];
    float s2a = g_s2[l], s2b = g_s2[32 + l];
    float t2a = g_t2[l], t2b = g_t2[32 + l];
    float inv = rsqrtf((float)cnt);

    // ---- pass 1: scores + max only ----
    float m = -INFINITY;
    const unsigned FULL = 0xffffffffu;
    for (int v = r0; v < r1; v++) {
        const __half* zr = g_z2 + (size_t)v * 64;
        float ha = fmaxf(fmaf(__half2float(zr[l]),      s2a, t2a), 0.f);
        float hb = fmaxf(fmaf(__half2float(zr[32 + l]), s2b, t2b), 0.f);
        float4 x4 = *(const float4*)(x_mod + (size_t)v * 128 + 4 * l);
        float part = ha * pt0 + hb * pt1
                   + x4.x * pb4.x + x4.y * pb4.y + x4.z * pb4.z + x4.w * pb4.w;
#pragma unroll
        for (int o = 16; o > 0; o >>= 1) part += __shfl_xor_sync(FULL, part, o);
        float X = part + cc;
        if (l == 0) g_X[v] = X;
        m = fmaxf(m, X);
    }
    __threadfence_block();
    __syncwarp();

    // ---- pass 2: denominator + pool together ----
    float d = 0.f;
    float4 p4 = make_float4(-INFINITY, -INFINITY, -INFINITY, -INFINITY);
    for (int v = r0; v < r1; v++) {
        float e = __expf((g_X[v] - m) * inv);            // broadcast load, off-chain
        d += e;
        float4 x4 = *(const float4*)(x_mod + (size_t)v * 128 + 4 * l);
        p4.x = fmaxf(p4.x, x4.x * e);
        p4.y = fmaxf(p4.y, x4.y * e);
        p4.z = fmaxf(p4.z, x4.z * e);
        p4.w = fmaxf(p4.w, x4.w * e);
    }
    float scale = tanhf(fmaxf(m, 0.f)) / (d + 1e-12f);   // gate / denom
    *(float4*)&op[4 * l] = make_float4(p4.x * scale, p4.y * scale,
                                       p4.z * scale, p4.w * scale);
    if (seen && l == 0) seen[gw] = 1.f;
}

// ---------------- launch ----------------------------------------------------
extern "C" void kernel_launch(void* const* d_in, const int* in_sizes, int n_in,
                              void* d_out, int out_size) {
    const float* x_main = (const float*)d_in[0];
    const float* x_mod  = (const float*)d_in[1];
    const float* x_proj = (const float*)d_in[2];
    const int*   csr    = (const int*)  d_in[3];
    const float* Wq     = (const float*)d_in[4];
    const float* bq     = (const float*)d_in[5];
    const float* W1     = (const float*)d_in[6];
    const float* b1     = (const float*)d_in[7];
    const float* g1     = (const float*)d_in[8];
    const float* beta1  = (const float*)d_in[9];
    const float* W2     = (const float*)d_in[10];
    const float* b2     = (const float*)d_in[11];
    const float* g2     = (const float*)d_in[12];
    const float* beta2  = (const float*)d_in[13];
    const float* Wk     = (const float*)d_in[14];
    const float* bk     = (const float*)d_in[15];

    float* out  = (float*)d_out;
    float* seen = (out_size >= NSEG * 129) ? out + (size_t)NSEG * 128 : nullptr;

    const int MLP2_SMEM = (64 * 264 + 2048 + 4096 + 256) * 4;   // 93184 B
    cudaFuncSetAttribute(k_mlp2, cudaFuncAttributeMaxDynamicSharedMemorySize, MLP2_SMEM);

    k_init  <<<1, 256>>>();
    k_gram2 <<<(VROWS + 1023) / 1024, 256>>>(x_proj);
    k_fing  <<<1, 64>>>(W1, b1, g1, beta1);
    k_mlp2  <<<(VROWS + 255) / 256, 256, MLP2_SMEM>>>(x_proj, W1, b1, W2, b2);
    k_fin2  <<<1, 64>>>(g2, beta2);
    k_q     <<<(NSEG + 63) / 64, 64>>>(x_main, Wq, bq);
    k_p     <<<(NSEG + 511) / 512, 128>>>(Wk, bk);
    k_seg   <<<(NSEG + 7) / 8, 256>>>(x_mod, csr, out, seen);
}